// round 1
// baseline (speedup 1.0000x reference)
#include <cuda_runtime.h>
#include <stdint.h>

// DiceFromLabelsLoss: joint-histogram formulation.
// J[b][yp][yt] over 100 bins per batch; c_pred/c_true are marginals,
// intersection is the diagonal. One conflict-free private-smem counter
// update per element pair, no atomics in the hot loop.

#define NBATCH  4
#define NCLS    10
#define NKEY    (NCLS * NCLS)          // 100
#define THREADS 512
#define CHUNKS_PER_BATCH 37
#define NBLK    (NBATCH * CHUNKS_PER_BATCH)   // 148 = one block per SM
#define SMEM_BYTES (NKEY * THREADS * 4)       // 204800 B

// Per-block partial joint histograms. Every slot is fully rewritten each
// launch -> no zeroing kernel, no global atomics, deterministic.
__device__ unsigned int g_part[NBLK * NKEY];

__global__ __launch_bounds__(THREADS, 1)
void dice_hist_kernel(const int4* __restrict__ yp,
                      const int4* __restrict__ yt,
                      int vecs_per_batch, int chunk)
{
    extern __shared__ unsigned int sm[];   // [NKEY][THREADS], bin-major
    const int tid = threadIdx.x;

    // Zero private counters (vectorized).
    int4* smz = reinterpret_cast<int4*>(sm);
    #pragma unroll
    for (int i = tid; i < NKEY * THREADS / 4; i += THREADS)
        smz[i] = make_int4(0, 0, 0, 0);
    __syncthreads();

    const int batch = blockIdx.x / CHUNKS_PER_BATCH;
    const int sub   = blockIdx.x % CHUNKS_PER_BATCH;
    const long base = (long)batch * vecs_per_batch;
    const int start = sub * chunk;
    const int end   = min(start + chunk, vecs_per_batch);

    // Hot loop: 2x LDG.128 per iter, 4 conflict-free counter updates.
    // Bank index of sm[key*512 + tid] is tid%32 for every key -> no conflicts.
    for (int i = start + tid; i < end; i += THREADS) {
        int4 p = yp[base + i];
        int4 t = yt[base + i];
        sm[(p.x * NCLS + t.x) * THREADS + tid] += 1u;
        sm[(p.y * NCLS + t.y) * THREADS + tid] += 1u;
        sm[(p.z * NCLS + t.z) * THREADS + tid] += 1u;
        sm[(p.w * NCLS + t.w) * THREADS + tid] += 1u;
    }
    __syncthreads();

    // Reduce 512 private copies -> 100 bins. Rotated index keeps the
    // 100 active lanes on distinct banks every step.
    if (tid < NKEY) {
        unsigned int s = 0;
        #pragma unroll 8
        for (int j = 0; j < THREADS; j++) {
            int jj = (j + tid) & (THREADS - 1);
            s += sm[tid * THREADS + jj];
        }
        g_part[blockIdx.x * NKEY + tid] = s;
    }
}

__global__ void dice_finalize_kernel(float* __restrict__ out)
{
    __shared__ unsigned int J[NBATCH * NKEY];
    __shared__ float ctv[NBATCH * NCLS];
    __shared__ float terms[NBATCH * (NCLS - 1)];
    const int tid = threadIdx.x;

    // Sum 37 block-partials per (batch, key).
    if (tid < NBATCH * NKEY) {
        int b = tid / NKEY, k = tid % NKEY;
        unsigned int s = 0;
        #pragma unroll
        for (int j = 0; j < CHUNKS_PER_BATCH; j++)
            s += g_part[(b * CHUNKS_PER_BATCH + j) * NKEY + k];
        J[tid] = s;
    }
    __syncthreads();

    // c_true marginal: ct[b][c] = sum_p J[b][p][c]
    if (tid < NBATCH * NCLS) {
        int b = tid / NCLS, c = tid % NCLS;
        unsigned int ct = 0;
        #pragma unroll
        for (int p = 0; p < NCLS; p++)
            ct += J[b * NKEY + p * NCLS + c];
        ctv[tid] = (float)ct;
    }
    __syncthreads();

    // Per-(batch, class>=1) weighted dice term.
    if (tid < NBATCH * (NCLS - 1)) {
        int b = tid / (NCLS - 1);
        int c = 1 + tid % (NCLS - 1);
        unsigned int cp = 0;
        #pragma unroll
        for (int t = 0; t < NCLS; t++)
            cp += J[b * NKEY + c * NCLS + t];
        float ct    = ctv[b * NCLS + c];
        float inter = (float)J[b * NKEY + c * NCLS + c];
        float denom = (float)cp + ct;
        float sumct = 0.0f;
        #pragma unroll
        for (int cc = 1; cc < NCLS; cc++)
            sumct += ctv[b * NCLS + cc];
        float term = 0.0f;
        if (denom > 0.0f)
            term = (ct / sumct * (1.0f / NBATCH)) * (2.0f * inter / denom);
        terms[tid] = term;
    }
    __syncthreads();

    // Serial final sum: fully deterministic.
    if (tid == 0) {
        float tot = 0.0f;
        for (int i = 0; i < NBATCH * (NCLS - 1); i++)
            tot += terms[i];
        out[0] = 1.0f - tot;
    }
}

extern "C" void kernel_launch(void* const* d_in, const int* in_sizes, int n_in,
                              void* d_out, int out_size)
{
    const int4* yp = (const int4*)d_in[0];
    const int4* yt = (const int4*)d_in[1];
    float* out = (float*)d_out;

    // total elements per tensor = NBATCH * vox; int4 vectors per batch:
    int vecs_per_batch = in_sizes[0] / (NBATCH * 4);
    int chunk = (vecs_per_batch + CHUNKS_PER_BATCH - 1) / CHUNKS_PER_BATCH;

    static bool attr_set = false;  // idempotent attribute opt-in (no device work)
    cudaFuncSetAttribute(dice_hist_kernel,
                         cudaFuncAttributeMaxDynamicSharedMemorySize, SMEM_BYTES);

    dice_hist_kernel<<<NBLK, THREADS, SMEM_BYTES>>>(yp, yt, vecs_per_batch, chunk);
    dice_finalize_kernel<<<1, THREADS>>>(out);
    (void)attr_set; (void)n_in; (void)out_size;
}

// round 3
// speedup vs baseline: 1.0065x; 1.0065x over previous
#include <cuda_runtime.h>
#include <stdint.h>

// DiceFromLabelsLoss: joint-histogram formulation, single fused kernel.
// J[b][yp][yt] over 100 bins per batch; c_pred/c_true are marginals,
// intersection is the diagonal. Conflict-free private-smem counters
// (bin-major [key][512]), no atomics in the hot loop. Loads are
// front-batched (8x LDG.128 per macro-iter) for MLP=8 per warp.
// Last block (threadfence + atomic ticket) finalizes the loss in-kernel.

#define NBATCH  4
#define NCLS    10
#define NKEY    (NCLS * NCLS)          // 100
#define THREADS 512
#define CHUNKS_PER_BATCH 37
#define NBLK    (NBATCH * CHUNKS_PER_BATCH)   // 148 = one block per SM
#define SMEM_BYTES (NKEY * THREADS * 4)       // 204800 B

__device__ unsigned int g_part[NBLK * NKEY];
__device__ unsigned int g_done;   // zero-init; last block resets to 0 -> deterministic

__device__ __forceinline__ void bump(unsigned int* sm, int4 p, int4 t, int tid)
{
    sm[(p.x * NCLS + t.x) * THREADS + tid] += 1u;
    sm[(p.y * NCLS + t.y) * THREADS + tid] += 1u;
    sm[(p.z * NCLS + t.z) * THREADS + tid] += 1u;
    sm[(p.w * NCLS + t.w) * THREADS + tid] += 1u;
}

__global__ __launch_bounds__(THREADS, 1)
void dice_fused_kernel(const int4* __restrict__ yp,
                       const int4* __restrict__ yt,
                       int vecs_per_batch, int chunk,
                       float* __restrict__ out)
{
    extern __shared__ unsigned int sm[];   // [NKEY][THREADS], bin-major
    const int tid = threadIdx.x;

    // Zero private counters (vectorized).
    int4* smz = reinterpret_cast<int4*>(sm);
    #pragma unroll
    for (int i = tid; i < NKEY * THREADS / 4; i += THREADS)
        smz[i] = make_int4(0, 0, 0, 0);
    __syncthreads();

    const int batch = blockIdx.x / CHUNKS_PER_BATCH;
    const int sub   = blockIdx.x % CHUNKS_PER_BATCH;
    const long base = (long)batch * vecs_per_batch;
    const int start = sub * chunk;
    const int end   = min(start + chunk, vecs_per_batch);

    // Main loop, unroll x4: front-batch 8 LDG.128 (MLP=8/warp), then 16
    // conflict-free counter updates (bank = tid%32 for every key).
    int i = start + tid;
    for (; i + 3 * THREADS < end; i += 4 * THREADS) {
        int4 p0 = yp[base + i];
        int4 p1 = yp[base + i +     THREADS];
        int4 p2 = yp[base + i + 2 * THREADS];
        int4 p3 = yp[base + i + 3 * THREADS];
        int4 t0 = yt[base + i];
        int4 t1 = yt[base + i +     THREADS];
        int4 t2 = yt[base + i + 2 * THREADS];
        int4 t3 = yt[base + i + 3 * THREADS];
        bump(sm, p0, t0, tid);
        bump(sm, p1, t1, tid);
        bump(sm, p2, t2, tid);
        bump(sm, p3, t3, tid);
    }
    for (; i < end; i += THREADS) {
        int4 p = yp[base + i];
        int4 t = yt[base + i];
        bump(sm, p, t, tid);
    }
    __syncthreads();

    // Reduce 512 private copies -> 100 bins. Warp-per-row + shuffle.
    const int wid  = tid >> 5, lane = tid & 31;
    for (int k = wid; k < NKEY; k += THREADS / 32) {
        unsigned int s = 0;
        #pragma unroll
        for (int j = lane; j < THREADS; j += 32)
            s += sm[k * THREADS + j];
        #pragma unroll
        for (int o = 16; o; o >>= 1)
            s += __shfl_down_sync(0xFFFFFFFFu, s, o);
        if (lane == 0)
            g_part[blockIdx.x * NKEY + k] = s;
    }

    // Last-block ticket.
    __threadfence();
    __shared__ bool is_last;
    if (tid == 0) {
        unsigned int old = atomicAdd(&g_done, 1u);
        is_last = (old == NBLK - 1);
    }
    __syncthreads();
    if (!is_last) return;
    __threadfence();

    // ---- Finalize (g_part is L2-hot) ----
    unsigned int* J   = sm;                          // [0, 400)
    float* ctv        = (float*)(sm + 512);          // [512, 552)
    float* terms      = (float*)(sm + 640);          // [640, 676)
    __syncthreads();

    if (tid < NBATCH * NKEY) {
        int b = tid / NKEY, k = tid % NKEY;
        unsigned int s = 0;
        #pragma unroll
        for (int j = 0; j < CHUNKS_PER_BATCH; j++)
            s += g_part[(b * CHUNKS_PER_BATCH + j) * NKEY + k];
        J[tid] = s;
    }
    __syncthreads();

    // c_true marginal: ct[b][c] = sum_p J[b][p][c]
    if (tid < NBATCH * NCLS) {
        int b = tid / NCLS, c = tid % NCLS;
        unsigned int ct = 0;
        #pragma unroll
        for (int p = 0; p < NCLS; p++)
            ct += J[b * NKEY + p * NCLS + c];
        ctv[tid] = (float)ct;
    }
    __syncthreads();

    if (tid < NBATCH * (NCLS - 1)) {
        int b = tid / (NCLS - 1);
        int c = 1 + tid % (NCLS - 1);
        unsigned int cp = 0;
        #pragma unroll
        for (int t = 0; t < NCLS; t++)
            cp += J[b * NKEY + c * NCLS + t];
        float ct    = ctv[b * NCLS + c];
        float inter = (float)J[b * NKEY + c * NCLS + c];
        float denom = (float)cp + ct;
        float sumct = 0.0f;
        #pragma unroll
        for (int cc = 1; cc < NCLS; cc++)
            sumct += ctv[b * NCLS + cc];
        float term = 0.0f;
        if (denom > 0.0f)
            term = (ct / sumct * (1.0f / NBATCH)) * (2.0f * inter / denom);
        terms[tid] = term;
    }
    __syncthreads();

    if (tid == 0) {
        float tot = 0.0f;
        for (int i2 = 0; i2 < NBATCH * (NCLS - 1); i2++)
            tot += terms[i2];
        out[0] = 1.0f - tot;
        g_done = 0;   // reset ticket -> deterministic across graph replays
    }
}

extern "C" void kernel_launch(void* const* d_in, const int* in_sizes, int n_in,
                              void* d_out, int out_size)
{
    const int4* yp = (const int4*)d_in[0];
    const int4* yt = (const int4*)d_in[1];
    float* out = (float*)d_out;

    int vecs_per_batch = in_sizes[0] / (NBATCH * 4);
    int chunk = (vecs_per_batch + CHUNKS_PER_BATCH - 1) / CHUNKS_PER_BATCH;

    cudaFuncSetAttribute(dice_fused_kernel,
                         cudaFuncAttributeMaxDynamicSharedMemorySize, SMEM_BYTES);

    dice_fused_kernel<<<NBLK, THREADS, SMEM_BYTES>>>(yp, yt, vecs_per_batch,
                                                     chunk, out);
    (void)n_in; (void)out_size;
}

// round 4
// speedup vs baseline: 1.0616x; 1.0548x over previous
#include <cuda_runtime.h>
#include <stdint.h>

// DiceFromLabelsLoss: joint-histogram, single fused kernel.
// Per-thread PRIVATE u8 counters [NKEY][512] in smem (51.2KB) -> 3 blocks/SM,
// 48 warps, 48KB of loads in flight. No atomics in the hot loop; u8 bumps
// are conflict-free (distinct bytes per lane). Epilogue: dp4a byte-sums ->
// integer atomicAdd into global joint histogram (exact, deterministic).
// Last block (ticket) computes the loss and resets state for graph replay.

#define NBATCH  4
#define NCLS    10
#define NKEY    (NCLS * NCLS)                 // 100
#define THREADS 512
#define CHUNKS_PER_BATCH 111
#define NBLK    (NBATCH * CHUNKS_PER_BATCH)   // 444 = 3 blocks x 148 SMs
#define SMEM_BYTES (NKEY * THREADS)           // 51200 B (u8 counters)

__device__ unsigned int g_joint[NBATCH * NKEY];  // zero-init; reset by last block
__device__ unsigned int g_done;                  // ticket; reset by last block

__device__ __forceinline__ void bump(unsigned char* sm, int4 p, int4 t, int tid)
{
    sm[(p.x * NCLS + t.x) * THREADS + tid] += 1;
    sm[(p.y * NCLS + t.y) * THREADS + tid] += 1;
    sm[(p.z * NCLS + t.z) * THREADS + tid] += 1;
    sm[(p.w * NCLS + t.w) * THREADS + tid] += 1;
}

__global__ __launch_bounds__(THREADS, 3)
void dice_fused_kernel(const int4* __restrict__ yp,
                       const int4* __restrict__ yt,
                       int vecs_per_batch, int chunk,
                       float* __restrict__ out)
{
    __shared__ unsigned char sm[SMEM_BYTES];     // [NKEY][THREADS] u8
    const int tid = threadIdx.x;

    // Zero private counters (int4-vectorized: 51200/16 = 3200 stores).
    int4* smz = reinterpret_cast<int4*>(sm);
    #pragma unroll
    for (int i = tid; i < SMEM_BYTES / 16; i += THREADS)
        smz[i] = make_int4(0, 0, 0, 0);
    __syncthreads();

    const int batch = blockIdx.x / CHUNKS_PER_BATCH;
    const int sub   = blockIdx.x % CHUNKS_PER_BATCH;
    const long base = (long)batch * vecs_per_batch;
    const int start = sub * chunk;
    const int end   = min(start + chunk, vecs_per_batch);

    // Hot loop: front-batch 8x LDG.128, then 16 conflict-free u8 bumps.
    int i = start + tid;
    for (; i + 3 * THREADS < end; i += 4 * THREADS) {
        int4 p0 = yp[base + i];
        int4 p1 = yp[base + i +     THREADS];
        int4 p2 = yp[base + i + 2 * THREADS];
        int4 p3 = yp[base + i + 3 * THREADS];
        int4 t0 = yt[base + i];
        int4 t1 = yt[base + i +     THREADS];
        int4 t2 = yt[base + i + 2 * THREADS];
        int4 t3 = yt[base + i + 3 * THREADS];
        bump(sm, p0, t0, tid);
        bump(sm, p1, t1, tid);
        bump(sm, p2, t2, tid);
        bump(sm, p3, t3, tid);
    }
    for (; i < end; i += THREADS) {
        int4 p = yp[base + i];
        int4 t = yt[base + i];
        bump(sm, p, t, tid);
    }
    __syncthreads();

    // Reduce 512 u8 per key via dp4a: key -> 128 u32 words, 4 words/lane.
    const unsigned int* sm32 = reinterpret_cast<const unsigned int*>(sm);
    const int wid = tid >> 5, lane = tid & 31;
    for (int k = wid; k < NKEY; k += THREADS / 32) {
        unsigned int s = 0;
        #pragma unroll
        for (int j = 0; j < 4; j++)
            s = __dp4a(sm32[k * (THREADS / 4) + j * 32 + lane], 0x01010101u, s);
        #pragma unroll
        for (int o = 16; o; o >>= 1)
            s += __shfl_down_sync(0xFFFFFFFFu, s, o);
        if (lane == 0)
            atomicAdd(&g_joint[batch * NKEY + k], s);   // integer: exact order-indep
    }

    // Last-block ticket.
    __threadfence();
    __shared__ bool is_last;
    if (tid == 0)
        is_last = (atomicAdd(&g_done, 1u) == NBLK - 1);
    __syncthreads();
    if (!is_last) return;
    __threadfence();

    // ---- Finalize from g_joint (L2-hot) ----
    __shared__ unsigned int J[NBATCH * NKEY];
    __shared__ float ctv[NBATCH * NCLS];
    __shared__ float terms[NBATCH * (NCLS - 1)];

    if (tid < NBATCH * NKEY)
        J[tid] = g_joint[tid];
    __syncthreads();

    // Reset state for next graph replay (after J snapshot).
    if (tid < NBATCH * NKEY) g_joint[tid] = 0u;
    if (tid == 0) g_done = 0u;

    // c_true marginal: ct[b][c] = sum_p J[b][p][c]
    if (tid < NBATCH * NCLS) {
        int b = tid / NCLS, c = tid % NCLS;
        unsigned int ct = 0;
        #pragma unroll
        for (int p = 0; p < NCLS; p++)
            ct += J[b * NKEY + p * NCLS + c];
        ctv[tid] = (float)ct;
    }
    __syncthreads();

    if (tid < NBATCH * (NCLS - 1)) {
        int b = tid / (NCLS - 1);
        int c = 1 + tid % (NCLS - 1);
        unsigned int cp = 0;
        #pragma unroll
        for (int t = 0; t < NCLS; t++)
            cp += J[b * NKEY + c * NCLS + t];
        float ct    = ctv[b * NCLS + c];
        float inter = (float)J[b * NKEY + c * NCLS + c];
        float denom = (float)cp + ct;
        float sumct = 0.0f;
        #pragma unroll
        for (int cc = 1; cc < NCLS; cc++)
            sumct += ctv[b * NCLS + cc];
        float term = 0.0f;
        if (denom > 0.0f)
            term = (ct / sumct * (1.0f / NBATCH)) * (2.0f * inter / denom);
        terms[tid] = term;
    }
    __syncthreads();

    if (tid == 0) {
        float tot = 0.0f;
        for (int i2 = 0; i2 < NBATCH * (NCLS - 1); i2++)
            tot += terms[i2];
        out[0] = 1.0f - tot;
    }
}

extern "C" void kernel_launch(void* const* d_in, const int* in_sizes, int n_in,
                              void* d_out, int out_size)
{
    const int4* yp = (const int4*)d_in[0];
    const int4* yt = (const int4*)d_in[1];
    float* out = (float*)d_out;

    int vecs_per_batch = in_sizes[0] / (NBATCH * 4);
    int chunk = (vecs_per_batch + CHUNKS_PER_BATCH - 1) / CHUNKS_PER_BATCH;

    dice_fused_kernel<<<NBLK, THREADS>>>(yp, yt, vecs_per_batch, chunk, out);
    (void)n_in; (void)out_size;
}

// round 5
// speedup vs baseline: 1.1222x; 1.0570x over previous
#include <cuda_runtime.h>
#include <cuda_pipeline_primitives.h>
#include <stdint.h>

// DiceFromLabelsLoss: joint-histogram, single fused kernel.
// cp.async (LDGSTS) 3-stage thread-local pipeline -> deep MLP without
// register pressure. Private u8 counters [NKEY][512] (conflict-free,
// no atomics in hot loop). dp4a byte-sum epilogue -> integer atomicAdd
// into global joint histogram (exact). Last block finalizes + resets.

#define NBATCH  4
#define NCLS    10
#define NKEY    (NCLS * NCLS)                 // 100
#define THREADS 512
#define CHUNKS_PER_BATCH 74
#define NBLK    (NBATCH * CHUNKS_PER_BATCH)   // 296 = 2 blocks x 148 SMs
#define NSTAGE  3
#define CNT_BYTES   (NKEY * THREADS)          // 51200
#define STAGE_BYTES (NSTAGE * 2 * THREADS * 16)   // 49152
#define SMEM_BYTES  (CNT_BYTES + STAGE_BYTES)     // 100352

__device__ unsigned int g_joint[NBATCH * NKEY];  // zero-init; reset by last block
__device__ unsigned int g_done;                  // ticket; reset by last block

__device__ __forceinline__ void bump(unsigned char* cnt, int4 p, int4 t, int tid)
{
    cnt[(p.x * NCLS + t.x) * THREADS + tid] += 1;
    cnt[(p.y * NCLS + t.y) * THREADS + tid] += 1;
    cnt[(p.z * NCLS + t.z) * THREADS + tid] += 1;
    cnt[(p.w * NCLS + t.w) * THREADS + tid] += 1;
}

__global__ __launch_bounds__(THREADS, 2)
void dice_fused_kernel(const int4* __restrict__ yp,
                       const int4* __restrict__ yt,
                       int vecs_per_batch, int chunk,
                       float* __restrict__ out)
{
    extern __shared__ unsigned char smem_raw[];
    unsigned char* cnt = smem_raw;                         // [NKEY][THREADS] u8
    int4* stage = (int4*)(smem_raw + CNT_BYTES);           // [NSTAGE][2][THREADS]
    const int tid = threadIdx.x;

    // Zero private counters (int4-vectorized).
    int4* smz = (int4*)cnt;
    #pragma unroll
    for (int i = tid; i < CNT_BYTES / 16; i += THREADS)
        smz[i] = make_int4(0, 0, 0, 0);
    __syncthreads();

    const int batch = blockIdx.x / CHUNKS_PER_BATCH;
    const int sub   = blockIdx.x % CHUNKS_PER_BATCH;
    const long base = (long)batch * vecs_per_batch;
    const int start = sub * chunk;
    const int end   = min(start + chunk, vecs_per_batch);
    const int span  = end - start;
    const int nst   = (span + THREADS - 1) / THREADS;      // stages this block

    // Prologue: issue NSTAGE-1 stages (one commit group per stage).
    #pragma unroll
    for (int s = 0; s < NSTAGE - 1; s++) {
        int g = start + s * THREADS + tid;
        if (g < end) {
            __pipeline_memcpy_async(&stage[(s * 2 + 0) * THREADS + tid], &yp[base + g], 16);
            __pipeline_memcpy_async(&stage[(s * 2 + 1) * THREADS + tid], &yt[base + g], 16);
        }
        __pipeline_commit();
    }

    // Steady state: fetch stage s+NSTAGE-1, then consume stage s.
    // Thread-local pipeline (each thread copies + consumes its own int4
    // pair) -> no __syncthreads in the hot loop.
    for (int s = 0; s < nst; s++) {
        int f = s + NSTAGE - 1;
        if (f < nst) {
            int g = start + f * THREADS + tid;
            int buf = f % NSTAGE;
            if (g < end) {
                __pipeline_memcpy_async(&stage[(buf * 2 + 0) * THREADS + tid], &yp[base + g], 16);
                __pipeline_memcpy_async(&stage[(buf * 2 + 1) * THREADS + tid], &yt[base + g], 16);
            }
        }
        __pipeline_commit();
        __pipeline_wait_prior(NSTAGE - 1);   // stage s resident

        int gc = start + s * THREADS + tid;
        if (gc < end) {
            int buf = s % NSTAGE;
            int4 p = stage[(buf * 2 + 0) * THREADS + tid];
            int4 t = stage[(buf * 2 + 1) * THREADS + tid];
            bump(cnt, p, t, tid);
        }
    }
    __syncthreads();

    // Reduce 512 u8 per key via dp4a: key -> 128 u32 words, 4 words/lane.
    const unsigned int* cnt32 = (const unsigned int*)cnt;
    const int wid = tid >> 5, lane = tid & 31;
    for (int k = wid; k < NKEY; k += THREADS / 32) {
        unsigned int s = 0;
        #pragma unroll
        for (int j = 0; j < 4; j++)
            s = __dp4a(cnt32[k * (THREADS / 4) + j * 32 + lane], 0x01010101u, s);
        #pragma unroll
        for (int o = 16; o; o >>= 1)
            s += __shfl_down_sync(0xFFFFFFFFu, s, o);
        if (lane == 0)
            atomicAdd(&g_joint[batch * NKEY + k], s);   // integer: order-independent
    }

    // Last-block ticket.
    __threadfence();
    __shared__ bool is_last;
    if (tid == 0)
        is_last = (atomicAdd(&g_done, 1u) == NBLK - 1);
    __syncthreads();
    if (!is_last) return;
    __threadfence();

    // ---- Finalize from g_joint (L2-hot) ----
    __shared__ unsigned int J[NBATCH * NKEY];
    __shared__ float ctv[NBATCH * NCLS];
    __shared__ float terms[NBATCH * (NCLS - 1)];

    if (tid < NBATCH * NKEY)
        J[tid] = g_joint[tid];
    __syncthreads();

    // Reset state for next graph replay (after snapshot).
    if (tid < NBATCH * NKEY) g_joint[tid] = 0u;
    if (tid == 0) g_done = 0u;

    // c_true marginal: ct[b][c] = sum_p J[b][p][c]
    if (tid < NBATCH * NCLS) {
        int b = tid / NCLS, c = tid % NCLS;
        unsigned int ct = 0;
        #pragma unroll
        for (int p = 0; p < NCLS; p++)
            ct += J[b * NKEY + p * NCLS + c];
        ctv[tid] = (float)ct;
    }
    __syncthreads();

    if (tid < NBATCH * (NCLS - 1)) {
        int b = tid / (NCLS - 1);
        int c = 1 + tid % (NCLS - 1);
        unsigned int cp = 0;
        #pragma unroll
        for (int t = 0; t < NCLS; t++)
            cp += J[b * NKEY + c * NCLS + t];
        float ct    = ctv[b * NCLS + c];
        float inter = (float)J[b * NKEY + c * NCLS + c];
        float denom = (float)cp + ct;
        float sumct = 0.0f;
        #pragma unroll
        for (int cc = 1; cc < NCLS; cc++)
            sumct += ctv[b * NCLS + cc];
        float term = 0.0f;
        if (denom > 0.0f)
            term = (ct / sumct * (1.0f / NBATCH)) * (2.0f * inter / denom);
        terms[tid] = term;
    }
    __syncthreads();

    if (tid == 0) {
        float tot = 0.0f;
        for (int i2 = 0; i2 < NBATCH * (NCLS - 1); i2++)
            tot += terms[i2];
        out[0] = 1.0f - tot;
    }
}

extern "C" void kernel_launch(void* const* d_in, const int* in_sizes, int n_in,
                              void* d_out, int out_size)
{
    const int4* yp = (const int4*)d_in[0];
    const int4* yt = (const int4*)d_in[1];
    float* out = (float*)d_out;

    int vecs_per_batch = in_sizes[0] / (NBATCH * 4);
    int chunk = (vecs_per_batch + CHUNKS_PER_BATCH - 1) / CHUNKS_PER_BATCH;

    cudaFuncSetAttribute(dice_fused_kernel,
                         cudaFuncAttributeMaxDynamicSharedMemorySize, SMEM_BYTES);

    dice_fused_kernel<<<NBLK, THREADS, SMEM_BYTES>>>(yp, yt, vecs_per_batch,
                                                     chunk, out);
    (void)n_in; (void)out_size;
}

// round 6
// speedup vs baseline: 1.1935x; 1.0635x over previous
#include <cuda_runtime.h>
#include <stdint.h>

// DiceFromLabelsLoss: joint-histogram, single fused kernel.
// Direct LDG.128 with explicit register software pipeline (prefetch next
// quad while bumping current) -> MLP=8/warp without smem staging.
// Private u8 counters [NKEY][512] (conflict-free, no atomics in hot loop).
// dp4a byte-sum epilogue -> integer atomicAdd into global joint histogram
// (exact, order-independent). Last block (ticket) finalizes + resets.

#define NBATCH  4
#define NCLS    10
#define NKEY    (NCLS * NCLS)                 // 100
#define THREADS 512
#define CHUNKS_PER_BATCH 74
#define NBLK    (NBATCH * CHUNKS_PER_BATCH)   // 296 = 2 blocks x 148 SMs
#define CNT_BYTES (NKEY * THREADS)            // 51200 B

__device__ unsigned int g_joint[NBATCH * NKEY];  // zero-init; reset by last block
__device__ unsigned int g_done;                  // ticket; reset by last block

__device__ __forceinline__ void bump(unsigned char* cnt, int4 p, int4 t, int tid)
{
    cnt[(p.x * NCLS + t.x) * THREADS + tid] += 1;
    cnt[(p.y * NCLS + t.y) * THREADS + tid] += 1;
    cnt[(p.z * NCLS + t.z) * THREADS + tid] += 1;
    cnt[(p.w * NCLS + t.w) * THREADS + tid] += 1;
}

__global__ __launch_bounds__(THREADS, 2)
void dice_fused_kernel(const int4* __restrict__ yp,
                       const int4* __restrict__ yt,
                       int vecs_per_batch, int chunk,
                       float* __restrict__ out)
{
    __shared__ unsigned char cnt[CNT_BYTES];     // [NKEY][THREADS] u8
    const int tid = threadIdx.x;

    // Zero private counters (int4-vectorized).
    int4* smz = (int4*)cnt;
    #pragma unroll
    for (int i = tid; i < CNT_BYTES / 16; i += THREADS)
        smz[i] = make_int4(0, 0, 0, 0);
    __syncthreads();

    const int batch = blockIdx.x / CHUNKS_PER_BATCH;
    const int sub   = blockIdx.x % CHUNKS_PER_BATCH;
    const long base = (long)batch * vecs_per_batch;
    const int start = sub * chunk;
    const int end   = min(start + chunk, vecs_per_batch);

    // Register software pipeline over quads of int4 (4 x 512 stride).
    // The 8 "next" loads have no consumer until after the current bumps,
    // so they issue front-batched: 8 LDG.128 in flight per thread slot.
    int i = start + tid;
    if (i + 3 * THREADS < end) {
        int4 cp0 = yp[base + i];
        int4 cp1 = yp[base + i +     THREADS];
        int4 cp2 = yp[base + i + 2 * THREADS];
        int4 cp3 = yp[base + i + 3 * THREADS];
        int4 ct0 = yt[base + i];
        int4 ct1 = yt[base + i +     THREADS];
        int4 ct2 = yt[base + i + 2 * THREADS];
        int4 ct3 = yt[base + i + 3 * THREADS];
        i += 4 * THREADS;
        for (; i + 3 * THREADS < end; i += 4 * THREADS) {
            int4 np0 = yp[base + i];
            int4 np1 = yp[base + i +     THREADS];
            int4 np2 = yp[base + i + 2 * THREADS];
            int4 np3 = yp[base + i + 3 * THREADS];
            int4 nt0 = yt[base + i];
            int4 nt1 = yt[base + i +     THREADS];
            int4 nt2 = yt[base + i + 2 * THREADS];
            int4 nt3 = yt[base + i + 3 * THREADS];
            bump(cnt, cp0, ct0, tid);
            bump(cnt, cp1, ct1, tid);
            bump(cnt, cp2, ct2, tid);
            bump(cnt, cp3, ct3, tid);
            cp0 = np0; cp1 = np1; cp2 = np2; cp3 = np3;
            ct0 = nt0; ct1 = nt1; ct2 = nt2; ct3 = nt3;
        }
        bump(cnt, cp0, ct0, tid);
        bump(cnt, cp1, ct1, tid);
        bump(cnt, cp2, ct2, tid);
        bump(cnt, cp3, ct3, tid);
    }
    for (; i < end; i += THREADS) {          // remainder
        int4 p = yp[base + i];
        int4 t = yt[base + i];
        bump(cnt, p, t, tid);
    }
    __syncthreads();

    // Reduce 512 u8 per key via dp4a: key -> 128 u32 words, 4 words/lane.
    const unsigned int* cnt32 = (const unsigned int*)cnt;
    const int wid = tid >> 5, lane = tid & 31;
    for (int k = wid; k < NKEY; k += THREADS / 32) {
        unsigned int s = 0;
        #pragma unroll
        for (int j = 0; j < 4; j++)
            s = __dp4a(cnt32[k * (THREADS / 4) + j * 32 + lane], 0x01010101u, s);
        #pragma unroll
        for (int o = 16; o; o >>= 1)
            s += __shfl_down_sync(0xFFFFFFFFu, s, o);
        if (lane == 0)
            atomicAdd(&g_joint[batch * NKEY + k], s);   // integer: order-independent
    }

    // Last-block ticket.
    __threadfence();
    __shared__ bool is_last;
    if (tid == 0)
        is_last = (atomicAdd(&g_done, 1u) == NBLK - 1);
    __syncthreads();
    if (!is_last) return;
    __threadfence();

    // ---- Finalize from g_joint (L2-hot) ----
    __shared__ unsigned int J[NBATCH * NKEY];
    __shared__ float ctv[NBATCH * NCLS];
    __shared__ float terms[NBATCH * (NCLS - 1)];

    if (tid < NBATCH * NKEY)
        J[tid] = g_joint[tid];
    __syncthreads();

    // Reset state for next graph replay (after snapshot).
    if (tid < NBATCH * NKEY) g_joint[tid] = 0u;
    if (tid == 0) g_done = 0u;

    // c_true marginal: ct[b][c] = sum_p J[b][p][c]
    if (tid < NBATCH * NCLS) {
        int b = tid / NCLS, c = tid % NCLS;
        unsigned int ct = 0;
        #pragma unroll
        for (int p = 0; p < NCLS; p++)
            ct += J[b * NKEY + p * NCLS + c];
        ctv[tid] = (float)ct;
    }
    __syncthreads();

    if (tid < NBATCH * (NCLS - 1)) {
        int b = tid / (NCLS - 1);
        int c = 1 + tid % (NCLS - 1);
        unsigned int cp = 0;
        #pragma unroll
        for (int t = 0; t < NCLS; t++)
            cp += J[b * NKEY + c * NCLS + t];
        float ct    = ctv[b * NCLS + c];
        float inter = (float)J[b * NKEY + c * NCLS + c];
        float denom = (float)cp + ct;
        float sumct = 0.0f;
        #pragma unroll
        for (int cc = 1; cc < NCLS; cc++)
            sumct += ctv[b * NCLS + cc];
        float term = 0.0f;
        if (denom > 0.0f)
            term = (ct / sumct * (1.0f / NBATCH)) * (2.0f * inter / denom);
        terms[tid] = term;
    }
    __syncthreads();

    if (tid == 0) {
        float tot = 0.0f;
        for (int i2 = 0; i2 < NBATCH * (NCLS - 1); i2++)
            tot += terms[i2];
        out[0] = 1.0f - tot;
    }
}

extern "C" void kernel_launch(void* const* d_in, const int* in_sizes, int n_in,
                              void* d_out, int out_size)
{
    const int4* yp = (const int4*)d_in[0];
    const int4* yt = (const int4*)d_in[1];
    float* out = (float*)d_out;

    int vecs_per_batch = in_sizes[0] / (NBATCH * 4);
    int chunk = (vecs_per_batch + CHUNKS_PER_BATCH - 1) / CHUNKS_PER_BATCH;

    dice_fused_kernel<<<NBLK, THREADS>>>(yp, yt, vecs_per_batch, chunk, out);
    (void)n_in; (void)out_size;
}